// round 8
// baseline (speedup 1.0000x reference)
#include <cuda_runtime.h>

// CubECLayr: Euler characteristic curve of sublevel cubical complex.
// x: (64,3,256,256) f32 -> out: (192,32) f32.
//
// Owner attribution (one signed weight per pixel), sign-mask compares
// ((a>b) <=> sign(b-a) as -1/0, NaN-free), shared compares between incident
// pixels, magic-FFMA binning. Histogram updates use shared-memory reduction
// atomics (no return value -> fire-and-forget REDS, no LDS dependency chain).

#define TPB 64
#define RPW 8
#define NB  32          // data in [0,1) => bins 0..31 only

// mask = -1 iff a > b, else 0
__device__ __forceinline__ int MGT(float a, float b) {
    return __float_as_int(b - a) >> 31;
}

__global__ void ecc_zero(float* __restrict__ out) {
    int i = blockIdx.x * blockDim.x + threadIdx.x;
    if (i < 192 * 32) out[i] = 0.0f;
}

__global__ __launch_bounds__(TPB, 16) void ecc_main(const float* __restrict__ x,
                                                    float* __restrict__ out) {
    __shared__ int sh[NB * TPB];   // h[k][tid], stride 64 -> bank=tid%32 (conflict-free)
    __shared__ int red[NB];

    const int tid  = threadIdx.x;
    const int lane = tid & 31;
    const int wid  = tid >> 5;
    const int img  = blockIdx.x >> 4;     // 192 images
    const int band = blockIdx.x & 15;     // 16 bands of 16 rows
    const int R0   = band * 16 + wid * RPW;
    const float* __restrict__ base = x + (size_t)img * 65536 + (size_t)R0 * 256 + lane * 8;
    char* const hb = (char*)sh + tid * 4; // per-thread histogram column base

#pragma unroll
    for (int k = 0; k < NB; ++k) sh[(k << 6) + tid] = 0;
    __syncthreads();   // REDS from any warp may target any column; publish zeros

    const float FINF = __int_as_float(0x7f800000);
    const unsigned FULL = 0xffffffffu;
    const bool lastStrip = (R0 + RPW) >= 256;

    float cur[8], nxt[8], curL, curR;
    int h[8], hm1;                 // horizontal masks
    int P[8], D[8], A[8];          // carried up-row masks (v, diag, anti-diag)
    int pdm1, pa8;

    // ---- load row R0, horizontal masks ----
    {
        float4 a4 = *(const float4*)(base);
        float4 b4 = *(const float4*)(base + 4);
        cur[0]=a4.x; cur[1]=a4.y; cur[2]=a4.z; cur[3]=a4.w;
        cur[4]=b4.x; cur[5]=b4.y; cur[6]=b4.z; cur[7]=b4.w;
    }
    curL = __shfl_up_sync(FULL, cur[7], 1);  if (lane == 0)  curL = FINF;
    curR = __shfl_down_sync(FULL, cur[0], 1); if (lane == 31) curR = FINF;
#pragma unroll
    for (int c = 0; c < 8; ++c) h[c] = MGT((c < 7) ? cur[c + 1] : curR, cur[c]);
    hm1 = MGT(cur[0], curL);

    // ---- carried masks from row R0-1 ----
    if (R0 > 0) {
        float pr[8];
        float4 a4 = *(const float4*)(base - 256);
        float4 b4 = *(const float4*)(base - 256 + 4);
        pr[0]=a4.x; pr[1]=a4.y; pr[2]=a4.z; pr[3]=a4.w;
        pr[4]=b4.x; pr[5]=b4.y; pr[6]=b4.z; pr[7]=b4.w;
        float prL = __shfl_up_sync(FULL, pr[7], 1);  if (lane == 0)  prL = FINF;
        float prR = __shfl_down_sync(FULL, pr[0], 1); if (lane == 31) prR = FINF;
#pragma unroll
        for (int c = 0; c < 8; ++c) {
            P[c] = MGT(cur[c], pr[c]);
            D[c] = MGT((c < 7) ? cur[c + 1] : curR, pr[c]);
            A[c] = (c > 0) ? MGT(cur[c - 1], pr[c]) : 0;
        }
        pdm1 = MGT(cur[0], prL);
        pa8  = MGT(cur[7], prR);
    } else {
#pragma unroll
        for (int c = 0; c < 8; ++c) { P[c] = 0; D[c] = 0; A[c] = 0; }
        pdm1 = 0; pa8 = 0;
    }

    // ---- preload row R0+1 (always < 256) ----
    {
        float4 a4 = *(const float4*)(base + 256);
        float4 b4 = *(const float4*)(base + 256 + 4);
        nxt[0]=a4.x; nxt[1]=a4.y; nxt[2]=a4.z; nxt[3]=a4.w;
        nxt[4]=b4.x; nxt[5]=b4.y; nxt[6]=b4.z; nxt[7]=b4.w;
    }

    // ---- main loop (fully unrolled: imm-offset loads, renamed rolls) ----
#pragma unroll
    for (int i = 0; i < RPW; ++i) {
        float dn[8];
#pragma unroll
        for (int c = 0; c < 8; ++c) dn[c] = nxt[c];
        float dnL = __shfl_up_sync(FULL, dn[7], 1);  if (lane == 0)  dnL = FINF;
        float dnR = __shfl_down_sync(FULL, dn[0], 1); if (lane == 31) dnR = FINF;

        // prefetch row R0+i+2 (compile-time except the final strip check)
        if (i + 2 < RPW) {
            const float* p = base + (i + 2) * 256;
            float4 a4 = *(const float4*)(p);
            float4 b4 = *(const float4*)(p + 4);
            nxt[0]=a4.x; nxt[1]=a4.y; nxt[2]=a4.z; nxt[3]=a4.w;
            nxt[4]=b4.x; nxt[5]=b4.y; nxt[6]=b4.z; nxt[7]=b4.w;
        } else if (i + 2 == RPW) {
            if (!lastStrip) {
                const float* p = base + (i + 2) * 256;
                float4 a4 = *(const float4*)(p);
                float4 b4 = *(const float4*)(p + 4);
                nxt[0]=a4.x; nxt[1]=a4.y; nxt[2]=a4.z; nxt[3]=a4.w;
                nxt[4]=b4.x; nxt[5]=b4.y; nxt[6]=b4.z; nxt[7]=b4.w;
            } else {
#pragma unroll
                for (int c = 0; c < 8; ++c) nxt[c] = FINF;
            }
        }

        int pend = 0;
#pragma unroll
        for (int c = 0; c < 8; ++c) {
            const float m = cur[c];
            const int v = MGT(dn[c], m);
            const int d = MGT((c < 7) ? dn[c + 1] : dnR, m);
            const int a = MGT((c > 0) ? dn[c - 1] : dnL, m);

            const int gl  = (c > 0) ? h[c - 1] : hm1;
            const int nh  = h[c];
            const int gu  = P[c];
            const int gul = (c > 0) ? D[c - 1] : pdm1;
            const int gur = (c < 7) ? A[c + 1] : pa8;

            const int s1 = gl &  gu & gul;
            const int s2 = gu & ~nh & gur;
            const int s3 = gl & ~v  & ~a;
            const int s4 = ~nh & ~v & ~d;

            // w = gl+gu-nh-v-1 - (s1+s2+s3+s4), shaped for 4x IADD3
            const int t1 = (gl + gu) - nh;
            const int t2 = (s1 + s2) + s3;
            const int t3 = (t1 - v) - t2;
            const int w  = (t3 - s4) - 1;

            // bin = ceil(31*m) via exact FFMA.RU magic; byte off = bits*256 == k*256
            const unsigned bits = __float_as_uint(__fmaf_ru(m, 31.0f, 8388608.0f));
            // fire-and-forget reduction: no return value -> REDS, no LDS chain
            atomicAdd((int*)(hb + bits * 256u), w);

            P[c] = v;
            if (c > 0) D[c - 1] = pend;
            pend = d;
            A[c] = a;
        }
        D[7] = pend;

        // halo masks for the next row (old curL/curR still live)
        pdm1 = MGT(dn[0], curL);
        pa8  = MGT(dn[7], curR);
        hm1  = MGT(dn[0], dnL);

        // roll window + fresh horizontal masks
#pragma unroll
        for (int c = 0; c < 8; ++c) cur[c] = dn[c];
        curL = dnL; curR = dnR;
#pragma unroll
        for (int c = 0; c < 8; ++c) h[c] = MGT((c < 7) ? cur[c + 1] : curR, cur[c]);
    }

    __syncthreads();

    // ---- block reduction: 2 half-sums per bin, lane-rotated (conflict-free) ----
    {
        const int b = tid >> 1, g = tid & 1;
        int s = 0;
#pragma unroll
        for (int j = 0; j < 32; ++j)
            s += sh[(b << 6) + (g << 5) + ((j + tid) & 31)];
        s += __shfl_xor_sync(FULL, s, 1);
        if (g == 0) red[b] = s;
    }
    __syncthreads();

    // ---- inclusive cumsum + exact integer-float atomic combine across bands ----
    if (tid < 32) {
        int acc = 0;
        for (int k = 0; k <= tid; ++k) acc += red[k];
        atomicAdd(&out[img * 32 + tid], (float)acc);
    }
}

extern "C" void kernel_launch(void* const* d_in, const int* in_sizes, int n_in,
                              void* d_out, int out_size) {
    const float* x = (const float*)d_in[0];
    float* out = (float*)d_out;
    ecc_zero<<<24, 256>>>(out);
    ecc_main<<<3072, TPB>>>(x, out);
}

// round 9
// speedup vs baseline: 1.0168x; 1.0168x over previous
#include <cuda_runtime.h>

// CubECLayr: Euler characteristic curve of sublevel cubical complex.
// x: (64,3,256,256) f32 -> out: (192,32) f32.
//
// Owner attribution (one signed weight per pixel), sign-mask compares
// ((a>b) <=> sign(b-a) as -1/0, NaN-free), shared compares between incident
// pixels, magic-FFMA binning, REDS histogram. NEW: 2-deep row prefetch
// (nxt, nxt2) so each row's loads are issued ~2 iterations (~640 cyc) before
// use, covering the ~577-cycle DRAM latency.

#define TPB 64
#define RPW 8
#define NB  32          // data in [0,1) => bins 0..31 only

// mask = -1 iff a > b, else 0
__device__ __forceinline__ int MGT(float a, float b) {
    return __float_as_int(b - a) >> 31;
}

__global__ void ecc_zero(float* __restrict__ out) {
    int i = blockIdx.x * blockDim.x + threadIdx.x;
    if (i < 192 * 32) out[i] = 0.0f;
}

__global__ __launch_bounds__(TPB, 14) void ecc_main(const float* __restrict__ x,
                                                    float* __restrict__ out) {
    __shared__ int sh[NB * TPB];   // h[k][tid], stride 64 -> bank=tid%32 (conflict-free)
    __shared__ int red[NB];

    const int tid  = threadIdx.x;
    const int lane = tid & 31;
    const int wid  = tid >> 5;
    const int img  = blockIdx.x >> 4;     // 192 images
    const int band = blockIdx.x & 15;     // 16 bands of 16 rows
    const int R0   = band * 16 + wid * RPW;
    const float* __restrict__ base = x + (size_t)img * 65536 + (size_t)R0 * 256 + lane * 8;
    char* const hb = (char*)sh + tid * 4; // per-thread histogram column base

#pragma unroll
    for (int k = 0; k < NB; ++k) sh[(k << 6) + tid] = 0;
    __syncthreads();

    const float FINF = __int_as_float(0x7f800000);
    const unsigned FULL = 0xffffffffu;
    const bool lastStrip = (R0 + RPW) >= 256;

    float cur[8], nxt[8], nxt2[8], curL, curR;
    int h[8], hm1;                 // horizontal masks
    int P[8], D[8], A[8];          // carried up-row masks (v, diag, anti-diag)
    int pdm1, pa8;

    // ---- load row R0, horizontal masks ----
    {
        float4 a4 = *(const float4*)(base);
        float4 b4 = *(const float4*)(base + 4);
        cur[0]=a4.x; cur[1]=a4.y; cur[2]=a4.z; cur[3]=a4.w;
        cur[4]=b4.x; cur[5]=b4.y; cur[6]=b4.z; cur[7]=b4.w;
    }
    curL = __shfl_up_sync(FULL, cur[7], 1);  if (lane == 0)  curL = FINF;
    curR = __shfl_down_sync(FULL, cur[0], 1); if (lane == 31) curR = FINF;
#pragma unroll
    for (int c = 0; c < 8; ++c) h[c] = MGT((c < 7) ? cur[c + 1] : curR, cur[c]);
    hm1 = MGT(cur[0], curL);

    // ---- carried masks from row R0-1 ----
    if (R0 > 0) {
        float pr[8];
        float4 a4 = *(const float4*)(base - 256);
        float4 b4 = *(const float4*)(base - 256 + 4);
        pr[0]=a4.x; pr[1]=a4.y; pr[2]=a4.z; pr[3]=a4.w;
        pr[4]=b4.x; pr[5]=b4.y; pr[6]=b4.z; pr[7]=b4.w;
        float prL = __shfl_up_sync(FULL, pr[7], 1);  if (lane == 0)  prL = FINF;
        float prR = __shfl_down_sync(FULL, pr[0], 1); if (lane == 31) prR = FINF;
#pragma unroll
        for (int c = 0; c < 8; ++c) {
            P[c] = MGT(cur[c], pr[c]);
            D[c] = MGT((c < 7) ? cur[c + 1] : curR, pr[c]);
            A[c] = (c > 0) ? MGT(cur[c - 1], pr[c]) : 0;
        }
        pdm1 = MGT(cur[0], prL);
        pa8  = MGT(cur[7], prR);
    } else {
#pragma unroll
        for (int c = 0; c < 8; ++c) { P[c] = 0; D[c] = 0; A[c] = 0; }
        pdm1 = 0; pa8 = 0;
    }

    // ---- preload rows R0+1 and R0+2 (both always < 256 for RPW=8, bands of 16) ----
    {
        float4 a4 = *(const float4*)(base + 256);
        float4 b4 = *(const float4*)(base + 256 + 4);
        nxt[0]=a4.x; nxt[1]=a4.y; nxt[2]=a4.z; nxt[3]=a4.w;
        nxt[4]=b4.x; nxt[5]=b4.y; nxt[6]=b4.z; nxt[7]=b4.w;
    }
    {
        float4 a4 = *(const float4*)(base + 512);
        float4 b4 = *(const float4*)(base + 512 + 4);
        nxt2[0]=a4.x; nxt2[1]=a4.y; nxt2[2]=a4.z; nxt2[3]=a4.w;
        nxt2[4]=b4.x; nxt2[5]=b4.y; nxt2[6]=b4.z; nxt2[7]=b4.w;
    }

    // ---- main loop (fully unrolled, 2-deep prefetch) ----
#pragma unroll
    for (int i = 0; i < RPW; ++i) {
        float dn[8];
#pragma unroll
        for (int c = 0; c < 8; ++c) dn[c] = nxt[c];
#pragma unroll
        for (int c = 0; c < 8; ++c) nxt[c] = nxt2[c];

        float dnL = __shfl_up_sync(FULL, dn[7], 1);  if (lane == 0)  dnL = FINF;
        float dnR = __shfl_down_sync(FULL, dn[0], 1); if (lane == 31) dnR = FINF;

        // prefetch row R0+i+3 into nxt2 (consumed as dn at iteration i+2)
        if (i + 3 < RPW) {
            const float* p = base + (i + 3) * 256;
            float4 a4 = *(const float4*)(p);
            float4 b4 = *(const float4*)(p + 4);
            nxt2[0]=a4.x; nxt2[1]=a4.y; nxt2[2]=a4.z; nxt2[3]=a4.w;
            nxt2[4]=b4.x; nxt2[5]=b4.y; nxt2[6]=b4.z; nxt2[7]=b4.w;
        } else if (i + 3 == RPW) {
            if (!lastStrip) {
                const float* p = base + (i + 3) * 256;
                float4 a4 = *(const float4*)(p);
                float4 b4 = *(const float4*)(p + 4);
                nxt2[0]=a4.x; nxt2[1]=a4.y; nxt2[2]=a4.z; nxt2[3]=a4.w;
                nxt2[4]=b4.x; nxt2[5]=b4.y; nxt2[6]=b4.z; nxt2[7]=b4.w;
            } else {
#pragma unroll
                for (int c = 0; c < 8; ++c) nxt2[c] = FINF;
            }
        }
        // i + 3 > RPW: nxt2 never consumed again; leave as-is.

        int pend = 0;
#pragma unroll
        for (int c = 0; c < 8; ++c) {
            const float m = cur[c];
            const int v = MGT(dn[c], m);
            const int d = MGT((c < 7) ? dn[c + 1] : dnR, m);
            const int a = MGT((c > 0) ? dn[c - 1] : dnL, m);

            const int gl  = (c > 0) ? h[c - 1] : hm1;
            const int nh  = h[c];
            const int gu  = P[c];
            const int gul = (c > 0) ? D[c - 1] : pdm1;
            const int gur = (c < 7) ? A[c + 1] : pa8;

            const int s1 = gl &  gu & gul;
            const int s2 = gu & ~nh & gur;
            const int s3 = gl & ~v  & ~a;
            const int s4 = ~nh & ~v & ~d;

            // w = gl+gu-nh-v-1 - (s1+s2+s3+s4), shaped for 4x IADD3
            const int t1 = (gl + gu) - nh;
            const int t2 = (s1 + s2) + s3;
            const int t3 = (t1 - v) - t2;
            const int w  = (t3 - s4) - 1;

            // bin = ceil(31*m) via exact FFMA.RU magic; byte off = bits*256 == k*256
            const unsigned bits = __float_as_uint(__fmaf_ru(m, 31.0f, 8388608.0f));
            atomicAdd((int*)(hb + bits * 256u), w);   // fire-and-forget REDS

            P[c] = v;
            if (c > 0) D[c - 1] = pend;
            pend = d;
            A[c] = a;
        }
        D[7] = pend;

        // halo masks for the next row (old curL/curR still live)
        pdm1 = MGT(dn[0], curL);
        pa8  = MGT(dn[7], curR);
        hm1  = MGT(dn[0], dnL);

        // roll window + fresh horizontal masks
#pragma unroll
        for (int c = 0; c < 8; ++c) cur[c] = dn[c];
        curL = dnL; curR = dnR;
#pragma unroll
        for (int c = 0; c < 8; ++c) h[c] = MGT((c < 7) ? cur[c + 1] : curR, cur[c]);
    }

    __syncthreads();

    // ---- block reduction: 2 half-sums per bin, lane-rotated (conflict-free) ----
    {
        const int b = tid >> 1, g = tid & 1;
        int s = 0;
#pragma unroll
        for (int j = 0; j < 32; ++j)
            s += sh[(b << 6) + (g << 5) + ((j + tid) & 31)];
        s += __shfl_xor_sync(FULL, s, 1);
        if (g == 0) red[b] = s;
    }
    __syncthreads();

    // ---- inclusive cumsum + exact integer-float atomic combine across bands ----
    if (tid < 32) {
        int acc = 0;
        for (int k = 0; k <= tid; ++k) acc += red[k];
        atomicAdd(&out[img * 32 + tid], (float)acc);
    }
}

extern "C" void kernel_launch(void* const* d_in, const int* in_sizes, int n_in,
                              void* d_out, int out_size) {
    const float* x = (const float*)d_in[0];
    float* out = (float*)d_out;
    ecc_zero<<<24, 256>>>(out);
    ecc_main<<<3072, TPB>>>(x, out);
}

// round 10
// speedup vs baseline: 1.0964x; 1.0783x over previous
#include <cuda_runtime.h>

// CubECLayr: Euler characteristic curve of sublevel cubical complex.
// x: (64,3,256,256) f32 -> out: (192,32) f32.
//
// Owner attribution (one signed weight per pixel), sign-mask compares
// ((a>b) <=> sign(b-a) as -1/0, NaN-free), shared compares between incident
// pixels, magic-FFMA binning, REDS histogram. This round: fully branchless
// lane-edge handling (SEL, no BSSY/BSYNC), explicit mod-3 row-buffer rotation
// (zero roll copies), register headroom via launch_bounds(64,12).

#define TPB 64
#define RPW 8
#define NB  32          // data in [0,1) => bins 0..31 only

// mask = -1 iff a > b, else 0
__device__ __forceinline__ int MGT(float a, float b) {
    return __float_as_int(b - a) >> 31;
}

__global__ void ecc_zero(float* __restrict__ out) {
    int i = blockIdx.x * blockDim.x + threadIdx.x;
    if (i < 192 * 32) out[i] = 0.0f;
}

__global__ __launch_bounds__(TPB, 12) void ecc_main(const float* __restrict__ x,
                                                    float* __restrict__ out) {
    __shared__ int sh[NB * TPB];   // h[k][tid], stride 64 -> bank=tid%32 (conflict-free)
    __shared__ int red[NB];

    const int tid  = threadIdx.x;
    const int lane = tid & 31;
    const int wid  = tid >> 5;
    const int img  = blockIdx.x >> 4;     // 192 images
    const int band = blockIdx.x & 15;     // 16 bands of 16 rows
    const int R0   = band * 16 + wid * RPW;
    const float* __restrict__ base = x + (size_t)img * 65536 + (size_t)R0 * 256 + lane * 8;
    char* const hb = (char*)sh + tid * 4; // per-thread histogram column base

#pragma unroll
    for (int k = 0; k < NB; ++k) sh[(k << 6) + tid] = 0;
    __syncthreads();

    const float FINF = __int_as_float(0x7f800000);
    const unsigned FULL = 0xffffffffu;
    const bool lastStrip = (R0 + RPW) >= 256;
    const bool l0  = (lane == 0);
    const bool l31 = (lane == 31);

    float buf[3][8];               // rotating row buffers (row r in buf[r%3])
    float curL, curR;
    int P[8], D[8], A[8];          // carried up-row masks (v, diag, anti-diag)
    int pdm1, pa8;

    // ---- load rows R0 -> buf[0], R0+1 -> buf[1] ----
    {
        float4 a4 = *(const float4*)(base);
        float4 b4 = *(const float4*)(base + 4);
        buf[0][0]=a4.x; buf[0][1]=a4.y; buf[0][2]=a4.z; buf[0][3]=a4.w;
        buf[0][4]=b4.x; buf[0][5]=b4.y; buf[0][6]=b4.z; buf[0][7]=b4.w;
    }
    {
        float4 a4 = *(const float4*)(base + 256);
        float4 b4 = *(const float4*)(base + 256 + 4);
        buf[1][0]=a4.x; buf[1][1]=a4.y; buf[1][2]=a4.z; buf[1][3]=a4.w;
        buf[1][4]=b4.x; buf[1][5]=b4.y; buf[1][6]=b4.z; buf[1][7]=b4.w;
    }
    curL = __shfl_up_sync(FULL, buf[0][7], 1);   curL = l0  ? FINF : curL;
    curR = __shfl_down_sync(FULL, buf[0][0], 1); curR = l31 ? FINF : curR;

    // ---- carried masks from row R0-1 ----
    if (R0 > 0) {
        float pr[8];
        float4 a4 = *(const float4*)(base - 256);
        float4 b4 = *(const float4*)(base - 256 + 4);
        pr[0]=a4.x; pr[1]=a4.y; pr[2]=a4.z; pr[3]=a4.w;
        pr[4]=b4.x; pr[5]=b4.y; pr[6]=b4.z; pr[7]=b4.w;
        float prL = __shfl_up_sync(FULL, pr[7], 1);   prL = l0  ? FINF : prL;
        float prR = __shfl_down_sync(FULL, pr[0], 1); prR = l31 ? FINF : prR;
#pragma unroll
        for (int c = 0; c < 8; ++c) {
            P[c] = MGT(buf[0][c], pr[c]);
            D[c] = MGT((c < 7) ? buf[0][c + 1] : curR, pr[c]);
            A[c] = (c > 0) ? MGT(buf[0][c - 1], pr[c]) : 0;
        }
        pdm1 = MGT(buf[0][0], prL);
        pa8  = MGT(buf[0][7], prR);
    } else {
#pragma unroll
        for (int c = 0; c < 8; ++c) { P[c] = 0; D[c] = 0; A[c] = 0; }
        pdm1 = 0; pa8 = 0;
    }

    // ---- main loop: explicit rotation, all indices compile-time ----
#pragma unroll
    for (int i = 0; i < RPW; ++i) {
        const int i0 = i % 3;          // current row
        const int i1 = (i + 1) % 3;    // down row
        const int i2 = (i + 2) % 3;    // prefetch slot

        float dnL = __shfl_up_sync(FULL, buf[i1][7], 1);   dnL = l0  ? FINF : dnL;
        float dnR = __shfl_down_sync(FULL, buf[i1][0], 1); dnR = l31 ? FINF : dnR;

        // prefetch row R0+i+2 into buf[i2]
        if (i + 2 < RPW) {
            const float* p = base + (i + 2) * 256;
            float4 a4 = *(const float4*)(p);
            float4 b4 = *(const float4*)(p + 4);
            buf[i2][0]=a4.x; buf[i2][1]=a4.y; buf[i2][2]=a4.z; buf[i2][3]=a4.w;
            buf[i2][4]=b4.x; buf[i2][5]=b4.y; buf[i2][6]=b4.z; buf[i2][7]=b4.w;
        } else if (i + 2 == RPW) {
            if (!lastStrip) {
                const float* p = base + (i + 2) * 256;
                float4 a4 = *(const float4*)(p);
                float4 b4 = *(const float4*)(p + 4);
                buf[i2][0]=a4.x; buf[i2][1]=a4.y; buf[i2][2]=a4.z; buf[i2][3]=a4.w;
                buf[i2][4]=b4.x; buf[i2][5]=b4.y; buf[i2][6]=b4.z; buf[i2][7]=b4.w;
            } else {
#pragma unroll
                for (int c = 0; c < 8; ++c) buf[i2][c] = FINF;
            }
        }
        // i + 2 > RPW: slot never consumed; skip (compile-time).

        // horizontal masks for the current row (fresh SSA values)
        int h[8];
#pragma unroll
        for (int c = 0; c < 8; ++c)
            h[c] = MGT((c < 7) ? buf[i0][c + 1] : curR, buf[i0][c]);
        const int hm1 = MGT(buf[i0][0], curL);

        int pend = 0;
#pragma unroll
        for (int c = 0; c < 8; ++c) {
            const float m = buf[i0][c];
            const int v = MGT(buf[i1][c], m);
            const int d = MGT((c < 7) ? buf[i1][c + 1] : dnR, m);
            const int a = MGT((c > 0) ? buf[i1][c - 1] : dnL, m);

            const int gl  = (c > 0) ? h[c - 1] : hm1;
            const int nh  = h[c];
            const int gu  = P[c];
            const int gul = (c > 0) ? D[c - 1] : pdm1;
            const int gur = (c < 7) ? A[c + 1] : pa8;

            const int s1 = gl &  gu & gul;
            const int s2 = gu & ~nh & gur;
            const int s3 = gl & ~v  & ~a;
            const int s4 = ~nh & ~v & ~d;

            // w = gl+gu-nh-v-1 - (s1+s2+s3+s4), shaped for 4x IADD3
            const int t1 = (gl + gu) - nh;
            const int t2 = (s1 + s2) + s3;
            const int t3 = (t1 - v) - t2;
            const int w  = (t3 - s4) - 1;

            // bin = ceil(31*m) via exact FFMA.RU magic; byte off = bits*256 == k*256
            const unsigned bits = __float_as_uint(__fmaf_ru(m, 31.0f, 8388608.0f));
            atomicAdd((int*)(hb + bits * 256u), w);   // fire-and-forget REDS

            P[c] = v;
            if (c > 0) D[c - 1] = pend;
            pend = d;
            A[c] = a;
        }
        D[7] = pend;

        // halo masks for the next row (old curL/curR still live)
        pdm1 = MGT(buf[i1][0], curL);
        pa8  = MGT(buf[i1][7], curR);

        curL = dnL; curR = dnR;      // scalar renames
    }

    __syncthreads();

    // ---- block reduction: 2 half-sums per bin, lane-rotated (conflict-free) ----
    {
        const int b = tid >> 1, g = tid & 1;
        int s = 0;
#pragma unroll
        for (int j = 0; j < 32; ++j)
            s += sh[(b << 6) + (g << 5) + ((j + tid) & 31)];
        s += __shfl_xor_sync(FULL, s, 1);
        if (g == 0) red[b] = s;
    }
    __syncthreads();

    // ---- inclusive cumsum + exact integer-float atomic combine across bands ----
    if (tid < 32) {
        int acc = 0;
        for (int k = 0; k <= tid; ++k) acc += red[k];
        atomicAdd(&out[img * 32 + tid], (float)acc);
    }
}

extern "C" void kernel_launch(void* const* d_in, const int* in_sizes, int n_in,
                              void* d_out, int out_size) {
    const float* x = (const float*)d_in[0];
    float* out = (float*)d_out;
    ecc_zero<<<24, 256>>>(out);
    ecc_main<<<3072, TPB>>>(x, out);
}